// round 1
// baseline (speedup 1.0000x reference)
#include <cuda_runtime.h>
#include <cuda_bf16.h>

#define BB 64
#define VV 64
#define TT 256
#define FF 64
#define B_PER_BLOCK 8
#define NTHREADS 256

__global__ __launch_bounds__(NTHREADS, 1)
void gnn_fused_kernel(const float* __restrict__ X,
                      const float* __restrict__ A,
                      const float* __restrict__ W,
                      float* __restrict__ out)
{
    // adj padded to 65 cols: reading adj[v][w] at fixed w across lanes v is
    // conflict-free (65v+w mod 32 distinct), unlike stride-64 (32-way conflict).
    __shared__ float adj[VV][VV + 1];          // ~16.6 KB
    __shared__ float w_sh[FF];
    __shared__ float hagg[B_PER_BLOCK][VV];

    const int t   = blockIdx.x;                // timestep 0..255
    const int bc  = blockIdx.y;                // batch chunk 0..7
    const int tid = threadIdx.x;

    if (tid < FF) w_sh[tid] = W[tid];

    // ---- adj[t] = sigmoid(A[t]) off-diagonal, 1 on diagonal ----
    const float* At = A + (size_t)t * VV * VV;
    #pragma unroll
    for (int i = tid; i < VV * VV; i += NTHREADS) {
        float a = At[i];
        float s = 1.0f / (1.0f + __expf(-a));
        int v = i >> 6, w = i & 63;
        adj[v][w] = (v == w) ? 1.0f : s;
    }
    __syncthreads();

    // ---- H_agg[bl][v] = sum_w adj[v][w] * X[b, w, t] ----
    // 8 b-locals * 64 v = 512 entries, 2 per thread. Within a warp all lanes
    // share b (e>>6 constant per 64-group), so xb[w*TT] is a broadcast load.
    #pragma unroll
    for (int k = 0; k < (B_PER_BLOCK * VV) / NTHREADS; ++k) {
        int e  = tid + k * NTHREADS;
        int bl = e >> 6;
        int v  = e & 63;
        int b  = bc * B_PER_BLOCK + bl;
        const float* xb = X + (size_t)b * VV * TT + t;   // X[b, w, t], stride TT
        float sum = 0.0f;
        #pragma unroll
        for (int w = 0; w < VV; ++w)
            sum = fmaf(adj[v][w], xb[(size_t)w * TT], sum);
        hagg[bl][v] = sum;
    }
    __syncthreads();

    // ---- epilogue: out[b,t,v,f] = leaky(H_agg[v] * W[f]), float4 stores ----
    #pragma unroll
    for (int bl = 0; bl < B_PER_BLOCK; ++bl) {
        int b = bc * B_PER_BLOCK + bl;
        float4* o = reinterpret_cast<float4*>(out + ((size_t)b * TT + t) * (VV * FF));
        #pragma unroll
        for (int i = 0; i < 4; ++i) {
            int idx = i * 1024 + tid * 4;          // element offset, 16B aligned
            int v = idx >> 6;
            int f = idx & 63;
            float h = hagg[bl][v];
            float4 wv = *reinterpret_cast<const float4*>(&w_sh[f]);
            float4 r;
            r.x = h * wv.x; r.y = h * wv.y; r.z = h * wv.z; r.w = h * wv.w;
            r.x = (r.x >= 0.0f) ? r.x : 0.01f * r.x;
            r.y = (r.y >= 0.0f) ? r.y : 0.01f * r.y;
            r.z = (r.z >= 0.0f) ? r.z : 0.01f * r.z;
            r.w = (r.w >= 0.0f) ? r.w : 0.01f * r.w;
            o[idx >> 2] = r;
        }
    }
}

extern "C" void kernel_launch(void* const* d_in, const int* in_sizes, int n_in,
                              void* d_out, int out_size) {
    const float* X = (const float*)d_in[0];   // [64, 64, 256]
    const float* A = (const float*)d_in[1];   // [256, 64, 64]
    const float* W = (const float*)d_in[2];   // [64, 1]
    float* out = (float*)d_out;               // [64, 256, 4096]
    (void)in_sizes; (void)n_in; (void)out_size;

    dim3 grid(TT, BB / B_PER_BLOCK);          // (256, 8)
    gnn_fused_kernel<<<grid, NTHREADS>>>(X, A, W, out);
}

// round 2
// speedup vs baseline: 1.4864x; 1.4864x over previous
#include <cuda_runtime.h>
#include <cuda_bf16.h>

#define BB 64
#define VV 64
#define TT 256
#define FF 64
#define NT1 256
#define NT2 256

// scratch: H_agg[b][t][v]  (4 MB) — __device__ global, allocation-free
__device__ float g_hagg[BB * TT * VV];

// ---------------------------------------------------------------------------
// k1: per timestep t, build adj = sigmoid(A_t)*(1-I)+I in smem, stage the
// whole X[:, :, t] slab (B x V = 4096 floats) in smem, then compute
// H_agg[b,t,v] = sum_w adj[v][w] * X[b,w,t] entirely from smem.
// ---------------------------------------------------------------------------
__global__ __launch_bounds__(NT1)
void k1_hagg(const float* __restrict__ X,
             const float* __restrict__ A,
             float* __restrict__ hout)
{
    __shared__ float adj[VV][VV + 1];   // +1 pad: adj[v][w] across lanes v conflict-free
    __shared__ float xs[BB][VV];        // xs[b][w] = X[b, w, t]

    const int t   = blockIdx.x;
    const int tid = threadIdx.x;

    // adj
    const float* At = A + (size_t)t * VV * VV;
    for (int i = tid; i < VV * VV; i += NT1) {
        float a = At[i];
        float s = 1.0f / (1.0f + __expf(-a));
        int v = i >> 6, w = i & 63;
        adj[v][w] = (v == w) ? 1.0f : s;
    }

    // stage X[:, :, t]  (strided 4B gathers; independent loads, latency hidden)
    for (int i = tid; i < BB * VV; i += NT1) {
        int b = i >> 6, w = i & 63;
        xs[b][w] = X[(size_t)b * VV * TT + (size_t)w * TT + t];
    }
    __syncthreads();

    // 4096 dot products, 16 per thread. Lanes in a warp share b, vary v:
    // adj[v][w] stride-65 => conflict-free; xs[b][w] => broadcast.
    for (int k = 0; k < (BB * VV) / NT1; ++k) {
        int e = tid + k * NT1;
        int b = e >> 6;
        int v = e & 63;
        float sum = 0.0f;
        #pragma unroll 16
        for (int w = 0; w < VV; ++w)
            sum = fmaf(adj[v][w], xs[b][w], sum);
        hout[((size_t)b * TT + t) * VV + v] = sum;   // coalesced per 64-group
    }
}

// ---------------------------------------------------------------------------
// k2: pure expansion/store stream. One block per (b,t): 4096 floats out.
// out[bt, v, f] = leaky(h[v] * W[f]); coalesced float4 stores.
// ---------------------------------------------------------------------------
__global__ __launch_bounds__(NT2)
void k2_expand(const float* __restrict__ hagg,
               const float* __restrict__ W,
               float* __restrict__ out)
{
    __shared__ float4 w4[FF / 4];
    __shared__ float  hs[VV];

    const int bt  = blockIdx.x;          // 0 .. B*T-1, == row index of hagg & out
    const int tid = threadIdx.x;

    if (tid < FF / 4) w4[tid] = reinterpret_cast<const float4*>(W)[tid];
    if (tid < VV)     hs[tid] = hagg[(size_t)bt * VV + tid];
    __syncthreads();

    float4* o = reinterpret_cast<float4*>(out + (size_t)bt * (VV * FF));
    #pragma unroll
    for (int j = 0; j < (VV * FF / 4) / NT2; ++j) {   // 4 iterations
        int p  = j * NT2 + tid;          // float4 index 0..1023, coalesced
        int v  = p >> 4;                 // 16 float4 per v-row
        int f4 = p & 15;
        float  h  = hs[v];
        float4 wv = w4[f4];
        float4 r;
        r.x = h * wv.x; r.y = h * wv.y; r.z = h * wv.z; r.w = h * wv.w;
        r.x = (r.x >= 0.0f) ? r.x : 0.01f * r.x;
        r.y = (r.y >= 0.0f) ? r.y : 0.01f * r.y;
        r.z = (r.z >= 0.0f) ? r.z : 0.01f * r.z;
        r.w = (r.w >= 0.0f) ? r.w : 0.01f * r.w;
        o[p] = r;
    }
}

extern "C" void kernel_launch(void* const* d_in, const int* in_sizes, int n_in,
                              void* d_out, int out_size) {
    const float* X = (const float*)d_in[0];   // [64, 64, 256]
    const float* A = (const float*)d_in[1];   // [256, 64, 64]
    const float* W = (const float*)d_in[2];   // [64, 1]
    float* out = (float*)d_out;               // [64, 256, 4096]
    (void)in_sizes; (void)n_in; (void)out_size;

    float* hagg;
    cudaGetSymbolAddress((void**)&hagg, g_hagg);   // no allocation; capture-safe

    k1_hagg <<<TT, NT1>>>(X, A, hagg);
    k2_expand<<<BB * TT, NT2>>>(hagg, W, out);
}

// round 4
// speedup vs baseline: 2.1701x; 1.4600x over previous
#include <cuda_runtime.h>
#include <cuda_bf16.h>

#define BB 64
#define VV 64
#define TT 256
#define FF 64
#define NT1 256
#define NT2 256

// scratch: H_agg[b][t][v]  (4 MB)
__device__ float g_hagg[BB * TT * VV];

// ---------------------------------------------------------------------------
// k1: per timestep t.
//   adj[v][w] = sigmoid(A[t,v,w]) off-diag, 1 on diag    (smem, 65-padded)
//   xsT[w][b] = X[b, w, t]                               (smem, transposed)
//   H[b][v]   = sum_w adj[v][w] * xsT[w][b]
// Register-tiled 4b x 4v per thread: 16 acc, per w: 1 LDS.128 + 4 LDS + 16 FMA.
// ---------------------------------------------------------------------------
__global__ __launch_bounds__(NT1)
void k1_hagg(const float* __restrict__ X,
             const float* __restrict__ A,
             float* __restrict__ hout)
{
    __shared__ float adj[VV][VV + 1];   // [v][w], +1 pad
    __shared__ float xsT[VV][VV];       // [w][b], b contiguous -> LDS.128

    const int t   = blockIdx.x;
    const int tid = threadIdx.x;

    // ---- adj = sigmoid(A_t) off-diagonal, 1 on diagonal ----
    const float* At = A + (size_t)t * VV * VV;
    #pragma unroll
    for (int k = 0; k < (VV * VV) / NT1; ++k) {
        int i = tid + k * NT1;
        int v = i >> 6, w = i & 63;
        float a = At[i];                              // coalesced
        float s = 1.0f / (1.0f + __expf(-a));
        adj[v][w] = (v == w) ? 1.0f : s;              // STS stride-65: conflict-free
    }

    // ---- stage X[:, :, t] transposed: xsT[w][b] ----
    #pragma unroll
    for (int k = 0; k < (BB * VV) / NT1; ++k) {
        int i = tid + k * NT1;
        int b = i & 63, w = i >> 6;
        xsT[w][b] = X[(size_t)b * VV * TT + (size_t)w * TT + t];  // STS contiguous in b
    }
    __syncthreads();

    // ---- 4b x 4v register tile per thread (256 threads x 16 = 4096 dots) ----
    const int bq = tid >> 4;            // 0..15
    const int vq = tid & 15;            // 0..15
    const int b0 = bq * 4;
    const int v0 = vq * 4;

    float acc[4][4];
    #pragma unroll
    for (int i = 0; i < 4; ++i)
        #pragma unroll
        for (int j = 0; j < 4; ++j) acc[i][j] = 0.0f;

    #pragma unroll 8
    for (int w = 0; w < VV; ++w) {
        float4 x4 = *reinterpret_cast<const float4*>(&xsT[w][b0]);  // 16B aligned
        float a0 = adj[v0 + 0][w];
        float a1 = adj[v0 + 1][w];
        float a2 = adj[v0 + 2][w];
        float a3 = adj[v0 + 3][w];
        acc[0][0] = fmaf(a0, x4.x, acc[0][0]);
        acc[0][1] = fmaf(a1, x4.x, acc[0][1]);
        acc[0][2] = fmaf(a2, x4.x, acc[0][2]);
        acc[0][3] = fmaf(a3, x4.x, acc[0][3]);
        acc[1][0] = fmaf(a0, x4.y, acc[1][0]);
        acc[1][1] = fmaf(a1, x4.y, acc[1][1]);
        acc[1][2] = fmaf(a2, x4.y, acc[1][2]);
        acc[1][3] = fmaf(a3, x4.y, acc[1][3]);
        acc[2][0] = fmaf(a0, x4.z, acc[2][0]);
        acc[2][1] = fmaf(a1, x4.z, acc[2][1]);
        acc[2][2] = fmaf(a2, x4.z, acc[2][2]);
        acc[2][3] = fmaf(a3, x4.z, acc[2][3]);
        acc[3][0] = fmaf(a0, x4.w, acc[3][0]);
        acc[3][1] = fmaf(a1, x4.w, acc[3][1]);
        acc[3][2] = fmaf(a2, x4.w, acc[3][2]);
        acc[3][3] = fmaf(a3, x4.w, acc[3][3]);
    }

    // ---- store: hout[(b*TT + t)*VV + v0..v0+3] as float4 per b ----
    #pragma unroll
    for (int i = 0; i < 4; ++i) {
        int b = b0 + i;
        float4 r = make_float4(acc[i][0], acc[i][1], acc[i][2], acc[i][3]);
        *reinterpret_cast<float4*>(&hout[((size_t)b * TT + t) * VV + v0]) = r;
    }
}

// ---------------------------------------------------------------------------
// k2: expansion/store stream. One block per (b,t): 4096 floats out.
// ---------------------------------------------------------------------------
__global__ __launch_bounds__(NT2)
void k2_expand(const float* __restrict__ hagg,
               const float* __restrict__ W,
               float* __restrict__ out)
{
    __shared__ float hs[VV];

    const int bt  = blockIdx.x;
    const int tid = threadIdx.x;

    if (tid < VV) hs[tid] = hagg[(size_t)bt * VV + tid];

    // f4 = (j*256 + tid) & 15 == tid & 15 : loop-invariant -> hoist W vector
    const float4 wv = reinterpret_cast<const float4*>(W)[tid & 15];
    __syncthreads();

    float4* o = reinterpret_cast<float4*>(out + (size_t)bt * (VV * FF));
    #pragma unroll
    for (int j = 0; j < (VV * FF / 4) / NT2; ++j) {   // 4 iterations
        int p = j * NT2 + tid;                        // float4 index, coalesced
        float h = hs[p >> 4];
        float4 r;
        r.x = h * wv.x; r.y = h * wv.y; r.z = h * wv.z; r.w = h * wv.w;
        r.x = (r.x >= 0.0f) ? r.x : 0.01f * r.x;
        r.y = (r.y >= 0.0f) ? r.y : 0.01f * r.y;
        r.z = (r.z >= 0.0f) ? r.z : 0.01f * r.z;
        r.w = (r.w >= 0.0f) ? r.w : 0.01f * r.w;
        __stcs(&o[p], r);                             // evict-first streaming store
    }
}

extern "C" void kernel_launch(void* const* d_in, const int* in_sizes, int n_in,
                              void* d_out, int out_size) {
    const float* X = (const float*)d_in[0];   // [64, 64, 256]
    const float* A = (const float*)d_in[1];   // [256, 64, 64]
    const float* W = (const float*)d_in[2];   // [64, 1]
    float* out = (float*)d_out;               // [64, 256, 4096]
    (void)in_sizes; (void)n_in; (void)out_size;

    float* hagg;
    cudaGetSymbolAddress((void**)&hagg, g_hagg);

    k1_hagg <<<TT, NT1>>>(X, A, hagg);
    k2_expand<<<BB * TT, NT2>>>(hagg, W, out);
}

// round 5
// speedup vs baseline: 2.4284x; 1.1190x over previous
#include <cuda_runtime.h>
#include <cuda_bf16.h>

#define BB 64
#define VV 64
#define TT 256
#define FF 64
#define NT  256
#define BPB 8     // batches per block

// ---------------------------------------------------------------------------
// Fused kernel. Block = (t, bc): one timestep, 8 batches.
//  Phase 1: adj = sigmoid(A_t)*(1-I)+I  (smem, 65-pad);  xs[bl][w] = X[b,w,t]
//           hs[bl][v] = sum_w adj[v][w]*xs[bl][w]   (2 dots/thread)
//  Phase 2: out[b,t,v,f] = leaky(hs[v]*W[f])  -> 8 x 16KB coalesced f4 stores
// Phase-1 issue work overlaps phase-2 store streams of co-resident blocks.
// ---------------------------------------------------------------------------
__global__ __launch_bounds__(NT)
void gnn_fused(const float* __restrict__ X,
               const float* __restrict__ A,
               const float* __restrict__ W,
               float* __restrict__ out)
{
    __shared__ float adj[VV][VV + 1];   // 16.6 KB, +1 pad: conflict-free v-strided reads
    __shared__ float xs[BPB][VV];       // 2 KB
    __shared__ float hs[BPB][VV];       // 2 KB

    const int t   = blockIdx.x;         // 0..255
    const int bc  = blockIdx.y;         // 0..7
    const int tid = threadIdx.x;
    const int b0  = bc * BPB;

    // ---- adj = sigmoid(A_t) off-diag, 1 on diag ----
    const float* At = A + (size_t)t * VV * VV;
    #pragma unroll
    for (int k = 0; k < (VV * VV) / NT; ++k) {       // 16 iters
        int i = tid + k * NT;
        int v = i >> 6, w = i & 63;
        float a = At[i];                              // coalesced (L2-hot: 8 blocks/t)
        float s = 1.0f / (1.0f + __expf(-a));
        adj[v][w] = (v == w) ? 1.0f : s;
    }

    // ---- stage xs[bl][w] = X[b0+bl, w, t] ----
    #pragma unroll
    for (int k = 0; k < (BPB * VV) / NT; ++k) {      // 2 iters
        int i  = tid + k * NT;
        int bl = i >> 6, w = i & 63;
        xs[bl][w] = X[((size_t)(b0 + bl) * VV + w) * TT + t];
    }
    __syncthreads();

    // ---- 2 dots per thread: (bl, v) and (bl, v+32) ----
    {
        int bl = tid >> 5;              // 0..7
        int v  = tid & 31;              // 0..31
        float acc0 = 0.0f, acc1 = 0.0f;
        #pragma unroll 8
        for (int w = 0; w < VV; ++w) {
            float x = xs[bl][w];                      // warp broadcast
            acc0 = fmaf(adj[v     ][w], x, acc0);     // stride-65: conflict-free
            acc1 = fmaf(adj[v + 32][w], x, acc1);
        }
        hs[bl][v]      = acc0;
        hs[bl][v + 32] = acc1;
    }

    // f index is loop-invariant per thread -> hoist W vector
    const float4 wv = reinterpret_cast<const float4*>(W)[tid & 15];
    __syncthreads();

    // ---- expansion: 8 rows x 16 KB, float4 streaming stores ----
    #pragma unroll
    for (int bl = 0; bl < BPB; ++bl) {
        float4* o = reinterpret_cast<float4*>(
            out + ((size_t)(b0 + bl) * TT + t) * (VV * FF));
        #pragma unroll
        for (int j = 0; j < (VV * FF / 4) / NT; ++j) {   // 4 iters
            int p = j * NT + tid;                        // float4 idx, coalesced
            float h = hs[bl][p >> 4];
            float4 r;
            r.x = h * wv.x; r.y = h * wv.y; r.z = h * wv.z; r.w = h * wv.w;
            r.x = (r.x >= 0.0f) ? r.x : 0.01f * r.x;
            r.y = (r.y >= 0.0f) ? r.y : 0.01f * r.y;
            r.z = (r.z >= 0.0f) ? r.z : 0.01f * r.z;
            r.w = (r.w >= 0.0f) ? r.w : 0.01f * r.w;
            __stcs(&o[p], r);                            // evict-first stream
        }
    }
}

extern "C" void kernel_launch(void* const* d_in, const int* in_sizes, int n_in,
                              void* d_out, int out_size) {
    const float* X = (const float*)d_in[0];   // [64, 64, 256]
    const float* A = (const float*)d_in[1];   // [256, 64, 64]
    const float* W = (const float*)d_in[2];   // [64, 1]
    float* out = (float*)d_out;               // [64, 256, 4096]
    (void)in_sizes; (void)n_in; (void)out_size;

    dim3 grid(TT, BB / BPB);                  // (256, 8)
    gnn_fused<<<grid, NT>>>(X, A, W, out);
}